// round 1
// baseline (speedup 1.0000x reference)
#include <cuda_runtime.h>

#define BATCH 8
#define CH    512
#define HW    4096
#define NMASK 1024
#define NCTX  3072
#define EPSF  1e-8f

// ---------------- scratch (static __device__ globals; no allocation) ----------
__device__ float g_Am[BATCH * CH * NMASK];            // A gathered [b][k][i]   16MB
__device__ float g_Bn[BATCH * CH * NCTX];             // B gathered [b][k][j]   48MB
__device__ float g_best[BATCH * NMASK * CH];          // best ctx col  [b][i][c]
__device__ float g_mskn[BATCH * NMASK * CH];          // normalized mask col [b][i][c]
__device__ float g_gen[BATCH * NMASK * CH];           // scan output [b][i][c]
__device__ float g_invall[BATCH * HW];                // 1/(||col||+eps) all points
__device__ float g_invc[BATCH * NCTX];
__device__ float g_invm[BATCH * NMASK];
__device__ float g_maxc[BATCH * NMASK];
__device__ unsigned long long g_packed[BATCH * NMASK];
__device__ int   g_imask[HW];

// ---------------- K1: column norms ------------------------------------------
__global__ void k_norms(const float* __restrict__ x) {
    int p = blockIdx.x * 256 + threadIdx.x;      // 0..4095
    int b = blockIdx.y;
    const float* base = x + (size_t)b * CH * HW + p;
    float s = 0.f;
#pragma unroll 8
    for (int c = 0; c < CH; c++) {
        float v = base[(size_t)c * HW];
        s += v * v;
    }
    g_invall[b * HW + p] = 1.f / (sqrtf(s) + EPSF);
}

// ---------------- K2: setup (imask, packed init, inv gathers) ---------------
__global__ void k_setup(const int* __restrict__ np, const int* __restrict__ mp) {
    int t = threadIdx.x;  // 1024 threads, 1 block
    for (int p = t; p < HW; p += 1024) g_imask[p] = -1;
    __syncthreads();
    g_imask[mp[t]] = t;
    for (int i = t; i < BATCH * NMASK; i += 1024) g_packed[i] = 0ull;
    for (int i = t; i < BATCH * NMASK; i += 1024) {
        int b = i / NMASK;
        g_invm[i] = g_invall[b * HW + mp[i % NMASK]];
    }
    for (int j = t; j < BATCH * NCTX; j += 1024) {
        int b = j / NCTX;
        g_invc[j] = g_invall[b * HW + np[j % NCTX]];
    }
}

// ---------------- K3: gather A (mask cols) and B (ctx cols), K-major --------
__global__ void k_gather(const float* __restrict__ x,
                         const int* __restrict__ np, const int* __restrict__ mp) {
    int k = blockIdx.x;         // 0..511
    int b = blockIdx.y;         // 0..7
    int t = threadIdx.x;        // 1024
    const float* row = x + ((size_t)b * CH + k) * HW;
    g_Am[((size_t)b * CH + k) * NMASK + t] = row[mp[t]];
#pragma unroll
    for (int j = t; j < NCTX; j += 1024)
        g_Bn[((size_t)b * CH + k) * NCTX + j] = row[np[j]];
}

// ---------------- K4: fp32 GEMM (f32x2 packed FFMA) + fused max/argmax ------
#define BM 128
#define BN 128
#define BK 8

__device__ __forceinline__ unsigned ford(float f) {
    unsigned u = __float_as_uint(f);
    return (u & 0x80000000u) ? ~u : (u | 0x80000000u);
}

__global__ void __launch_bounds__(256, 2) k_gemm() {
    __shared__ __align__(16) float As[BK][BM];
    __shared__ __align__(16) float Bs[BK][BN];
    __shared__ unsigned long long red[BM][16];

    int b  = blockIdx.z;
    int i0 = blockIdx.y * BM;
    int j0 = blockIdx.x * BN;
    int tid = threadIdx.x;
    int tx = tid & 15, ty = tid >> 4;
    int lk = tid >> 5;            // 0..7  (k row of tile)
    int lv = (tid & 31) * 4;      // 0..124 (vec4 offset)

    const float* A  = g_Am + (size_t)b * CH * NMASK;
    const float* Bp = g_Bn + (size_t)b * CH * NCTX;

    unsigned long long acc[8][4];
#pragma unroll
    for (int r = 0; r < 8; r++)
#pragma unroll
        for (int q = 0; q < 4; q++) acc[r][q] = 0ull;

    for (int k0 = 0; k0 < CH; k0 += BK) {
        float4 ra = *(const float4*)(A  + (size_t)(k0 + lk) * NMASK + i0 + lv);
        float4 rb = *(const float4*)(Bp + (size_t)(k0 + lk) * NCTX  + j0 + lv);
        __syncthreads();
        *(float4*)&As[lk][lv] = ra;
        *(float4*)&Bs[lk][lv] = rb;
        __syncthreads();
#pragma unroll
        for (int kk = 0; kk < BK; kk++) {
            float a[8];
            *(float4*)&a[0] = *(const float4*)&As[kk][ty * 8];
            *(float4*)&a[4] = *(const float4*)&As[kk][ty * 8 + 4];
            unsigned long long b2[4];
#pragma unroll
            for (int q = 0; q < 4; q++)
                b2[q] = *(const unsigned long long*)&Bs[kk][tx * 8 + 2 * q];
#pragma unroll
            for (int r = 0; r < 8; r++) {
                unsigned long long a2;
                asm("mov.b64 %0, {%1, %1};" : "=l"(a2) : "r"(__float_as_uint(a[r])));
#pragma unroll
                for (int q = 0; q < 4; q++)
                    asm("fma.rn.f32x2 %0, %1, %2, %0;"
                        : "+l"(acc[r][q]) : "l"(a2), "l"(b2[q]));
            }
        }
    }

    // epilogue: scale by inv_c, per-row max/argmax, merge
    float invc[8];
#pragma unroll
    for (int q = 0; q < 8; q++) invc[q] = g_invc[b * NCTX + j0 + tx * 8 + q];

#pragma unroll
    for (int r = 0; r < 8; r++) {
        unsigned long long bestp = 0ull;
#pragma unroll
        for (int q = 0; q < 4; q++) {
            float lo = __uint_as_float((unsigned)acc[r][q]);
            float hi = __uint_as_float((unsigned)(acc[r][q] >> 32));
            float v0 = lo * invc[2 * q];
            float v1 = hi * invc[2 * q + 1];
            int jg = j0 + tx * 8 + 2 * q;
            unsigned long long p0 = ((unsigned long long)ford(v0) << 32) | (unsigned)(~(unsigned)jg);
            unsigned long long p1 = ((unsigned long long)ford(v1) << 32) | (unsigned)(~(unsigned)(jg + 1));
            if (p0 > bestp) bestp = p0;
            if (p1 > bestp) bestp = p1;
        }
        red[ty * 8 + r][tx] = bestp;
    }
    __syncthreads();
    if (tid < BM) {
        unsigned long long m = red[tid][0];
#pragma unroll
        for (int q = 1; q < 16; q++) if (red[tid][q] > m) m = red[tid][q];
        atomicMax(&g_packed[b * NMASK + i0 + tid], m);
    }
}

// ---------------- K5: finalize pick + gather best & normalized mask cols ----
__global__ void k_finalize(const float* __restrict__ x,
                           const int* __restrict__ np, const int* __restrict__ mp) {
    int i = blockIdx.x;   // 0..1023
    int b = blockIdx.y;   // 0..7
    int t = threadIdx.x;  // 128
    __shared__ int s_col, s_mcol;
    __shared__ float s_invm;
    if (t == 0) {
        unsigned long long pk = g_packed[b * NMASK + i];
        unsigned j  = ~(unsigned)pk;
        unsigned ov = (unsigned)(pk >> 32);
        unsigned fb = (ov & 0x80000000u) ? (ov & 0x7fffffffu) : ~ov;
        float val = __uint_as_float(fb);
        float im  = g_invm[b * NMASK + i];
        g_maxc[b * NMASK + i] = val * im;
        s_col = np[j];
        s_mcol = mp[i];
        s_invm = im;
    }
    __syncthreads();
    int col = s_col, mcol = s_mcol;
    float im = s_invm;
    const float* xb = x + (size_t)b * CH * HW;
    size_t o = ((size_t)b * NMASK + i) * CH;
    for (int c = t; c < CH; c += 128) {
        g_best[o + c] = xb[(size_t)c * HW + col];
        g_mskn[o + c] = xb[(size_t)c * HW + mcol] * im;
    }
}

// ---------------- K6: sequential coherent scan (1 warp per batch) -----------
__global__ void k_scan() {
    int b = blockIdx.x;
    int lane = threadIdx.x;   // 32
    float q[16];
#pragma unroll
    for (int e = 0; e < 16; e++) q[e] = 0.f;

    const float* MN = g_mskn + (size_t)b * NMASK * CH;
    const float* BS = g_best + (size_t)b * NMASK * CH;
    float*       GE = g_gen  + (size_t)b * NMASK * CH;
    const float* MX = g_maxc + b * NMASK;

    for (int i = 0; i < NMASK; i++) {
        size_t off = (size_t)i * CH + lane * 16;
        float mn[16], bs[16];
#pragma unroll
        for (int u = 0; u < 4; u++) {
            float4 a = *(const float4*)(MN + off + u * 4);
            mn[u * 4 + 0] = a.x; mn[u * 4 + 1] = a.y; mn[u * 4 + 2] = a.z; mn[u * 4 + 3] = a.w;
            float4 c = *(const float4*)(BS + off + u * 4);
            bs[u * 4 + 0] = c.x; bs[u * 4 + 1] = c.y; bs[u * 4 + 2] = c.z; bs[u * 4 + 3] = c.w;
        }
        float s1 = 0.f, s2 = 0.f;
#pragma unroll
        for (int e = 0; e < 16; e++) {
            s1 += q[e] * q[e];
            s2 += mn[e] * q[e];
        }
#pragma unroll
        for (int o = 16; o; o >>= 1) {
            s1 += __shfl_xor_sync(0xffffffffu, s1, o);
            s2 += __shfl_xor_sync(0xffffffffu, s2, o);
        }
        float d  = fmaxf(s2, 0.f) / (sqrtf(s1) + EPSF);
        float mx = MX[i];
        float it = 1.f / (d + mx + EPSF);
#pragma unroll
        for (int e = 0; e < 16; e++) q[e] = (d * q[e] + mx * bs[e]) * it;
#pragma unroll
        for (int u = 0; u < 4; u++) {
            float4 w;
            w.x = q[u * 4 + 0]; w.y = q[u * 4 + 1]; w.z = q[u * 4 + 2]; w.w = q[u * 4 + 3];
            *(float4*)(GE + off + u * 4) = w;
        }
    }
}

// ---------------- K7: assemble output ---------------------------------------
__global__ void k_out(const float* __restrict__ x, float* __restrict__ out) {
    int idx = blockIdx.x * 256 + threadIdx.x;      // < 16,777,216
    int p = idx & (HW - 1);
    int c = (idx >> 12) & (CH - 1);
    int b = idx >> 21;
    int mi = g_imask[p];
    float v = (mi >= 0) ? g_gen[(((size_t)b * NMASK) + mi) * CH + c] : x[idx];
    out[idx] = v;
}

// ---------------- launch -----------------------------------------------------
extern "C" void kernel_launch(void* const* d_in, const int* in_sizes, int n_in,
                              void* d_out, int out_size) {
    const float* x  = (const float*)d_in[0];
    const int*   np = (const int*)d_in[2];   // nonmask_point_idx (3072)
    const int*   mp = (const int*)d_in[3];   // mask_point_idx    (1024)
    float*       out = (float*)d_out;

    k_norms   <<<dim3(HW / 256, BATCH), 256>>>(x);
    k_setup   <<<1, 1024>>>(np, mp);
    k_gather  <<<dim3(CH, BATCH), 1024>>>(x, np, mp);
    k_gemm    <<<dim3(NCTX / BN, NMASK / BM, BATCH), 256>>>();
    k_finalize<<<dim3(NMASK, BATCH), 128>>>(x, np, mp);
    k_scan    <<<BATCH, 32>>>();
    k_out     <<<(BATCH * CH * HW) / 256, 256>>>(x, out);
}

// round 2
// speedup vs baseline: 1.5310x; 1.5310x over previous
#include <cuda_runtime.h>

#define BATCH 8
#define CH    512
#define HW    4096
#define NMASK 1024
#define NCTX  3072
#define EPSF  1e-8f

// ---------------- scratch (static __device__ globals; no allocation) ----------
__device__ float g_Am[BATCH * CH * NMASK];            // A gathered [b][k][i]
__device__ float g_Bn[BATCH * CH * NCTX];             // B gathered [b][k][j]
__device__ float g_best[BATCH * NMASK * CH];          // best ctx col  [b][i][c]
__device__ float g_mskn[BATCH * NMASK * CH];          // normalized mask col [b][i][c]
__device__ float g_gen[BATCH * NMASK * CH];           // scan output [b][i][c]
__device__ float g_invall[BATCH * HW];
__device__ float g_invc[BATCH * NCTX];
__device__ float g_invm[BATCH * NMASK];
__device__ float g_maxc[BATCH * NMASK];
__device__ unsigned long long g_packed[BATCH * NMASK];
__device__ int   g_imask[HW];

// ---------------- K1: column norms ------------------------------------------
__global__ void k_norms(const float* __restrict__ x) {
    int p = blockIdx.x * 256 + threadIdx.x;
    int b = blockIdx.y;
    const float* base = x + (size_t)b * CH * HW + p;
    float s = 0.f;
#pragma unroll 8
    for (int c = 0; c < CH; c++) {
        float v = base[(size_t)c * HW];
        s += v * v;
    }
    g_invall[b * HW + p] = 1.f / (sqrtf(s) + EPSF);
}

// ---------------- K2: setup --------------------------------------------------
__global__ void k_setup(const int* __restrict__ np, const int* __restrict__ mp) {
    int t = threadIdx.x;  // 1024 threads, 1 block
    for (int p = t; p < HW; p += 1024) g_imask[p] = -1;
    __syncthreads();
    g_imask[mp[t]] = t;
    for (int i = t; i < BATCH * NMASK; i += 1024) g_packed[i] = 0ull;
    for (int i = t; i < BATCH * NMASK; i += 1024) {
        int b = i / NMASK;
        g_invm[i] = g_invall[b * HW + mp[i % NMASK]];
    }
    for (int j = t; j < BATCH * NCTX; j += 1024) {
        int b = j / NCTX;
        g_invc[j] = g_invall[b * HW + np[j % NCTX]];
    }
}

// ---------------- K3: gather A (mask cols) and B (ctx cols), K-major --------
__global__ void k_gather(const float* __restrict__ x,
                         const int* __restrict__ np, const int* __restrict__ mp) {
    int k = blockIdx.x;
    int b = blockIdx.y;
    int t = threadIdx.x;        // 1024
    const float* row = x + ((size_t)b * CH + k) * HW;
    g_Am[((size_t)b * CH + k) * NMASK + t] = row[mp[t]];
#pragma unroll
    for (int j = t; j < NCTX; j += 1024)
        g_Bn[((size_t)b * CH + k) * NCTX + j] = row[np[j]];
}

// ---------------- K4: fp32 GEMM v2 (cp.async pipeline, f32x2 FFMA) ----------
#define BM 128
#define BN 128
#define BK 16
#define NT (CH / BK)

__device__ __forceinline__ unsigned ford(float f) {
    unsigned u = __float_as_uint(f);
    return (u & 0x80000000u) ? ~u : (u | 0x80000000u);
}

__device__ __forceinline__ void cp16(void* sdst, const void* gsrc) {
    unsigned saddr = (unsigned)__cvta_generic_to_shared(sdst);
    asm volatile("cp.async.ca.shared.global [%0], [%1], 16;\n" :: "r"(saddr), "l"(gsrc));
}

__global__ void __launch_bounds__(256, 2) k_gemm() {
    __shared__ __align__(16) float As[2][BK][BM];
    __shared__ __align__(16) float Bs[2][BK][BN];

    int b  = blockIdx.z;
    int i0 = blockIdx.y * BM;
    int j0 = blockIdx.x * BN;
    int tid = threadIdx.x;
    int tx = tid & 15, ty = tid >> 4;   // ty also = load row kr
    int cA = tx * 4;

    const float* A  = g_Am + (size_t)b * CH * NMASK + i0;
    const float* Bp = g_Bn + (size_t)b * CH * NCTX  + j0;

    unsigned long long acc[8][4];
#pragma unroll
    for (int r = 0; r < 8; r++)
#pragma unroll
        for (int q = 0; q < 4; q++) acc[r][q] = 0ull;

    // tile copy: 16 rows x 128 cols, each thread 2x16B per operand
#define COPY_TILE(t)                                                          \
    do {                                                                      \
        int s_ = (t) & 1;                                                     \
        const float* ga = A  + (size_t)((t) * BK + ty) * NMASK + cA;          \
        const float* gb = Bp + (size_t)((t) * BK + ty) * NCTX  + cA;          \
        cp16(&As[s_][ty][cA],      ga);                                       \
        cp16(&As[s_][ty][64 + cA], ga + 64);                                  \
        cp16(&Bs[s_][ty][cA],      gb);                                       \
        cp16(&Bs[s_][ty][64 + cA], gb + 64);                                  \
        asm volatile("cp.async.commit_group;\n");                             \
    } while (0)

    COPY_TILE(0);
    COPY_TILE(1);

#pragma unroll 1
    for (int t = 0; t < NT; t++) {
        if (t < NT - 1) asm volatile("cp.async.wait_group 1;\n");
        else            asm volatile("cp.async.wait_group 0;\n");
        __syncthreads();
        int s = t & 1;
#pragma unroll
        for (int kk = 0; kk < BK; kk++) {
            float4 a0 = *(const float4*)&As[s][kk][ty * 4];
            float4 a1 = *(const float4*)&As[s][kk][64 + ty * 4];
            ulonglong2 bv0 = *(const ulonglong2*)&Bs[s][kk][tx * 4];
            ulonglong2 bv1 = *(const ulonglong2*)&Bs[s][kk][64 + tx * 4];
            float ar[8] = {a0.x, a0.y, a0.z, a0.w, a1.x, a1.y, a1.z, a1.w};
            unsigned long long bq[4] = {bv0.x, bv0.y, bv1.x, bv1.y};
#pragma unroll
            for (int r = 0; r < 8; r++) {
                unsigned long long a2;
                asm("mov.b64 %0, {%1, %1};" : "=l"(a2) : "r"(__float_as_uint(ar[r])));
#pragma unroll
                for (int q = 0; q < 4; q++)
                    asm("fma.rn.f32x2 %0, %1, %2, %0;"
                        : "+l"(acc[r][q]) : "l"(a2), "l"(bq[q]));
            }
        }
        __syncthreads();
        if (t + 2 < NT) COPY_TILE(t + 2);
    }

    // epilogue: scale by inv_c, pack (val, ~j), half-warp reduce over tx, atomicMax
    float invc[8];
#pragma unroll
    for (int g = 0; g < 2; g++)
#pragma unroll
        for (int e = 0; e < 4; e++)
            invc[g * 4 + e] = g_invc[b * NCTX + j0 + g * 64 + tx * 4 + e];

#pragma unroll
    for (int r = 0; r < 8; r++) {
        int irow = (r < 4) ? (ty * 4 + r) : (64 + ty * 4 + (r - 4));
        unsigned long long bp = 0ull;
#pragma unroll
        for (int q = 0; q < 4; q++) {
            float lo = __uint_as_float((unsigned)acc[r][q]);
            float hi = __uint_as_float((unsigned)(acc[r][q] >> 32));
            float v0 = lo * invc[q * 2];
            float v1 = hi * invc[q * 2 + 1];
            int jg = j0 + ((q >> 1) * 64) + tx * 4 + (q & 1) * 2;
            unsigned long long p0 = ((unsigned long long)ford(v0) << 32) | (unsigned)(~(unsigned)jg);
            unsigned long long p1 = ((unsigned long long)ford(v1) << 32) | (unsigned)(~(unsigned)(jg + 1));
            if (p0 > bp) bp = p0;
            if (p1 > bp) bp = p1;
        }
#pragma unroll
        for (int o = 1; o < 16; o <<= 1) {
            unsigned long long other = __shfl_xor_sync(0xffffffffu, bp, o);
            if (other > bp) bp = other;
        }
        if (tx == 0) atomicMax(&g_packed[b * NMASK + i0 + irow], bp);
    }
}

// ---------------- K5: finalize pick + gather from L2-hot scratch ------------
__global__ void k_finalize() {
    int i = blockIdx.x;   // 0..1023
    int b = blockIdx.y;
    int t = threadIdx.x;  // 128
    __shared__ int s_j;
    __shared__ float s_invm;
    if (t == 0) {
        unsigned long long pk = g_packed[b * NMASK + i];
        unsigned j  = ~(unsigned)pk;
        unsigned ov = (unsigned)(pk >> 32);
        unsigned fb = (ov & 0x80000000u) ? (ov & 0x7fffffffu) : ~ov;
        float val = __uint_as_float(fb);
        float im  = g_invm[b * NMASK + i];
        g_maxc[b * NMASK + i] = val * im;
        s_j = (int)j;
        s_invm = im;
    }
    __syncthreads();
    int jj = s_j;
    float im = s_invm;
    const float* Am = g_Am + (size_t)b * CH * NMASK;
    const float* Bn = g_Bn + (size_t)b * CH * NCTX;
    size_t o = ((size_t)b * NMASK + i) * CH;
#pragma unroll
    for (int c = t; c < CH; c += 128) {
        g_best[o + c] = Bn[(size_t)c * NCTX + jj];
        g_mskn[o + c] = Am[(size_t)c * NMASK + i] * im;
    }
}

// ---------------- K6: sequential scan, register-double-buffered -------------
__device__ __forceinline__ void scan_load(const float* MN, const float* BS,
                                          size_t off, float* mn, float* bs) {
#pragma unroll
    for (int u = 0; u < 4; u++) {
        float4 a = *(const float4*)(MN + off + u * 4);
        mn[u * 4 + 0] = a.x; mn[u * 4 + 1] = a.y; mn[u * 4 + 2] = a.z; mn[u * 4 + 3] = a.w;
        float4 c = *(const float4*)(BS + off + u * 4);
        bs[u * 4 + 0] = c.x; bs[u * 4 + 1] = c.y; bs[u * 4 + 2] = c.z; bs[u * 4 + 3] = c.w;
    }
}

__device__ __forceinline__ void scan_step(float* q, const float* mn, const float* bs,
                                          float mx, float* GE, size_t off) {
    float s1a = 0.f, s1b = 0.f, s2a = 0.f, s2b = 0.f;
#pragma unroll
    for (int e = 0; e < 16; e += 2) {
        s1a += q[e] * q[e];
        s1b += q[e + 1] * q[e + 1];
        s2a += mn[e] * q[e];
        s2b += mn[e + 1] * q[e + 1];
    }
    float s1 = s1a + s1b, s2 = s2a + s2b;
#pragma unroll
    for (int o = 16; o; o >>= 1) {
        s1 += __shfl_xor_sync(0xffffffffu, s1, o);
        s2 += __shfl_xor_sync(0xffffffffu, s2, o);
    }
    float nrm = (s1 > 0.f) ? s1 * rsqrtf(s1) : 0.f;
    float d  = __fdividef(fmaxf(s2, 0.f), nrm + EPSF);
    float it = __fdividef(1.f, d + mx + EPSF);
    float dit = d * it, mit = mx * it;
#pragma unroll
    for (int e = 0; e < 16; e++) q[e] = dit * q[e] + mit * bs[e];
#pragma unroll
    for (int u = 0; u < 4; u++) {
        float4 w;
        w.x = q[u * 4 + 0]; w.y = q[u * 4 + 1]; w.z = q[u * 4 + 2]; w.w = q[u * 4 + 3];
        *(float4*)(GE + off + u * 4) = w;
    }
}

__global__ void k_scan() {
    int b = blockIdx.x;
    int lane = threadIdx.x;   // 32
    float q[16];
#pragma unroll
    for (int e = 0; e < 16; e++) q[e] = 0.f;

    const float* MN = g_mskn + (size_t)b * NMASK * CH;
    const float* BS = g_best + (size_t)b * NMASK * CH;
    float*       GE = g_gen  + (size_t)b * NMASK * CH;
    const float* MX = g_maxc + b * NMASK;
    size_t lo = (size_t)lane * 16;

    float mnA[16], bsA[16], mnB[16], bsB[16];
    scan_load(MN, BS, lo, mnA, bsA);
    scan_load(MN, BS, (size_t)CH + lo, mnB, bsB);

#pragma unroll 1
    for (int i = 0; i < NMASK; i += 2) {
        float mxA = MX[i], mxB = MX[i + 1];
        scan_step(q, mnA, bsA, mxA, GE, (size_t)i * CH + lo);
        if (i + 2 < NMASK) scan_load(MN, BS, (size_t)(i + 2) * CH + lo, mnA, bsA);
        scan_step(q, mnB, bsB, mxB, GE, (size_t)(i + 1) * CH + lo);
        if (i + 3 < NMASK) scan_load(MN, BS, (size_t)(i + 3) * CH + lo, mnB, bsB);
    }
}

// ---------------- K7: assemble output ---------------------------------------
__global__ void k_out(const float* __restrict__ x, float* __restrict__ out) {
    int idx = blockIdx.x * 256 + threadIdx.x;
    int p = idx & (HW - 1);
    int c = (idx >> 12) & (CH - 1);
    int b = idx >> 21;
    int mi = g_imask[p];
    float v = (mi >= 0) ? g_gen[(((size_t)b * NMASK) + mi) * CH + c] : x[idx];
    out[idx] = v;
}

// ---------------- launch -----------------------------------------------------
extern "C" void kernel_launch(void* const* d_in, const int* in_sizes, int n_in,
                              void* d_out, int out_size) {
    const float* x  = (const float*)d_in[0];
    const int*   np = (const int*)d_in[2];
    const int*   mp = (const int*)d_in[3];
    float*       out = (float*)d_out;

    k_norms   <<<dim3(HW / 256, BATCH), 256>>>(x);
    k_setup   <<<1, 1024>>>(np, mp);
    k_gather  <<<dim3(CH, BATCH), 1024>>>(x, np, mp);
    k_gemm    <<<dim3(NCTX / BN, NMASK / BM, BATCH), 256>>>();
    k_finalize<<<dim3(NMASK, BATCH), 128>>>();
    k_scan    <<<BATCH, 32>>>();
    k_out     <<<(BATCH * CH * HW) / 256, 256>>>(x, out);
}

// round 3
// speedup vs baseline: 1.7074x; 1.1152x over previous
#include <cuda_runtime.h>

#define BATCH 8
#define CH    512
#define HW    4096
#define NMASK 1024
#define NCTX  3072
#define EPSF  1e-8f
#define NSPLIT 4

// ---------------- scratch (static __device__ globals; no allocation) ----------
__device__ float g_Am[BATCH * CH * NMASK];            // A gathered [b][k][i]
__device__ float g_Bn[BATCH * CH * NCTX];             // B gathered [b][k][j]
__device__ float g_best[BATCH * NMASK * CH];
__device__ float g_mskn[BATCH * NMASK * CH];
__device__ float g_gen[BATCH * NMASK * CH];
__device__ float g_part[NSPLIT][BATCH * HW];
__device__ float g_invall[BATCH * HW];
__device__ float g_invc[BATCH * NCTX];
__device__ float g_invm[BATCH * NMASK];
__device__ float g_maxc[BATCH * NMASK];
__device__ unsigned long long g_packed[BATCH * NMASK];
__device__ int   g_imask[HW];

// ---------------- K1a: partial column norms (c-split for occupancy) ---------
__global__ void k_part(const float* __restrict__ x) {
    int p = blockIdx.x * 256 + threadIdx.x;
    int b = blockIdx.y;
    int z = blockIdx.z;
    const float* base = x + ((size_t)b * CH + (size_t)z * (CH / NSPLIT)) * HW + p;
    float s = 0.f;
#pragma unroll 8
    for (int c = 0; c < CH / NSPLIT; c++) {
        float v = base[(size_t)c * HW];
        s += v * v;
    }
    g_part[z][b * HW + p] = s;
}

// ---------------- K1b: combine partials -> invall ---------------------------
__global__ void k_invall() {
    int i = blockIdx.x * 256 + threadIdx.x;   // BATCH*HW/256 = 128 blocks
    float s = g_part[0][i] + g_part[1][i] + g_part[2][i] + g_part[3][i];
    g_invall[i] = 1.f / (sqrtf(s) + EPSF);
}

// ---------------- K2: setup --------------------------------------------------
__global__ void k_setup(const int* __restrict__ np, const int* __restrict__ mp) {
    int t = threadIdx.x;  // 1024 threads, 1 block
    for (int p = t; p < HW; p += 1024) g_imask[p] = -1;
    __syncthreads();
    g_imask[mp[t]] = t;
    for (int i = t; i < BATCH * NMASK; i += 1024) g_packed[i] = 0ull;
    for (int i = t; i < BATCH * NMASK; i += 1024) {
        int b = i / NMASK;
        g_invm[i] = g_invall[b * HW + mp[i % NMASK]];
    }
    for (int j = t; j < BATCH * NCTX; j += 1024) {
        int b = j / NCTX;
        g_invc[j] = g_invall[b * HW + np[j % NCTX]];
    }
}

// ---------------- K3: gather A (mask cols) and B (ctx cols), K-major --------
__global__ void k_gather(const float* __restrict__ x,
                         const int* __restrict__ np, const int* __restrict__ mp) {
    int k = blockIdx.x;
    int b = blockIdx.y;
    int t = threadIdx.x;        // 1024
    const float* row = x + ((size_t)b * CH + k) * HW;
    g_Am[((size_t)b * CH + k) * NMASK + t] = row[mp[t]];
#pragma unroll
    for (int j = t; j < NCTX; j += 1024)
        g_Bn[((size_t)b * CH + k) * NCTX + j] = row[np[j]];
}

// ---------------- K4: fp32 GEMM (cp.async pipeline, f32x2 FFMA) -------------
#define BM 128
#define BN 128
#define BK 16
#define NT (CH / BK)

__device__ __forceinline__ unsigned ford(float f) {
    unsigned u = __float_as_uint(f);
    return (u & 0x80000000u) ? ~u : (u | 0x80000000u);
}

__device__ __forceinline__ void cp16(void* sdst, const void* gsrc) {
    unsigned saddr = (unsigned)__cvta_generic_to_shared(sdst);
    asm volatile("cp.async.ca.shared.global [%0], [%1], 16;\n" :: "r"(saddr), "l"(gsrc));
}

__global__ void __launch_bounds__(256, 2) k_gemm() {
    __shared__ __align__(16) float As[2][BK][BM];
    __shared__ __align__(16) float Bs[2][BK][BN];

    int b  = blockIdx.z;
    int i0 = blockIdx.y * BM;
    int j0 = blockIdx.x * BN;
    int tid = threadIdx.x;
    int tx = tid & 15, ty = tid >> 4;
    int cA = tx * 4;

    const float* A  = g_Am + (size_t)b * CH * NMASK + i0;
    const float* Bp = g_Bn + (size_t)b * CH * NCTX  + j0;

    unsigned long long acc[8][4];
#pragma unroll
    for (int r = 0; r < 8; r++)
#pragma unroll
        for (int q = 0; q < 4; q++) acc[r][q] = 0ull;

#define COPY_TILE(t)                                                          \
    do {                                                                      \
        int s_ = (t) & 1;                                                     \
        const float* ga = A  + (size_t)((t) * BK + ty) * NMASK + cA;          \
        const float* gb = Bp + (size_t)((t) * BK + ty) * NCTX  + cA;          \
        cp16(&As[s_][ty][cA],      ga);                                       \
        cp16(&As[s_][ty][64 + cA], ga + 64);                                  \
        cp16(&Bs[s_][ty][cA],      gb);                                       \
        cp16(&Bs[s_][ty][64 + cA], gb + 64);                                  \
        asm volatile("cp.async.commit_group;\n");                             \
    } while (0)

    COPY_TILE(0);
    COPY_TILE(1);

#pragma unroll 1
    for (int t = 0; t < NT; t++) {
        if (t < NT - 1) asm volatile("cp.async.wait_group 1;\n");
        else            asm volatile("cp.async.wait_group 0;\n");
        __syncthreads();
        int s = t & 1;
#pragma unroll
        for (int kk = 0; kk < BK; kk++) {
            float4 a0 = *(const float4*)&As[s][kk][ty * 4];
            float4 a1 = *(const float4*)&As[s][kk][64 + ty * 4];
            ulonglong2 bv0 = *(const ulonglong2*)&Bs[s][kk][tx * 4];
            ulonglong2 bv1 = *(const ulonglong2*)&Bs[s][kk][64 + tx * 4];
            float ar[8] = {a0.x, a0.y, a0.z, a0.w, a1.x, a1.y, a1.z, a1.w};
            unsigned long long bq[4] = {bv0.x, bv0.y, bv1.x, bv1.y};
#pragma unroll
            for (int r = 0; r < 8; r++) {
                unsigned long long a2;
                asm("mov.b64 %0, {%1, %1};" : "=l"(a2) : "r"(__float_as_uint(ar[r])));
#pragma unroll
                for (int q = 0; q < 4; q++)
                    asm("fma.rn.f32x2 %0, %1, %2, %0;"
                        : "+l"(acc[r][q]) : "l"(a2), "l"(bq[q]));
            }
        }
        __syncthreads();
        if (t + 2 < NT) COPY_TILE(t + 2);
    }

    float invc[8];
#pragma unroll
    for (int g = 0; g < 2; g++)
#pragma unroll
        for (int e = 0; e < 4; e++)
            invc[g * 4 + e] = g_invc[b * NCTX + j0 + g * 64 + tx * 4 + e];

#pragma unroll
    for (int r = 0; r < 8; r++) {
        int irow = (r < 4) ? (ty * 4 + r) : (64 + ty * 4 + (r - 4));
        unsigned long long bp = 0ull;
#pragma unroll
        for (int q = 0; q < 4; q++) {
            float lo = __uint_as_float((unsigned)acc[r][q]);
            float hi = __uint_as_float((unsigned)(acc[r][q] >> 32));
            float v0 = lo * invc[q * 2];
            float v1 = hi * invc[q * 2 + 1];
            int jg = j0 + ((q >> 1) * 64) + tx * 4 + (q & 1) * 2;
            unsigned long long p0 = ((unsigned long long)ford(v0) << 32) | (unsigned)(~(unsigned)jg);
            unsigned long long p1 = ((unsigned long long)ford(v1) << 32) | (unsigned)(~(unsigned)(jg + 1));
            if (p0 > bp) bp = p0;
            if (p1 > bp) bp = p1;
        }
#pragma unroll
        for (int o = 1; o < 16; o <<= 1) {
            unsigned long long other = __shfl_xor_sync(0xffffffffu, bp, o);
            if (other > bp) bp = other;
        }
        if (tx == 0) atomicMax(&g_packed[b * NMASK + i0 + irow], bp);
    }
}

// ---------------- K5: finalize pick + gather from L2-hot scratch ------------
__global__ void k_finalize() {
    int i = blockIdx.x;
    int b = blockIdx.y;
    int t = threadIdx.x;  // 256
    __shared__ int s_j;
    __shared__ float s_invm;
    if (t == 0) {
        unsigned long long pk = g_packed[b * NMASK + i];
        unsigned j  = ~(unsigned)pk;
        unsigned ov = (unsigned)(pk >> 32);
        unsigned fb = (ov & 0x80000000u) ? (ov & 0x7fffffffu) : ~ov;
        float val = __uint_as_float(fb);
        float im  = g_invm[b * NMASK + i];
        g_maxc[b * NMASK + i] = val * im;
        s_j = (int)j;
        s_invm = im;
    }
    __syncthreads();
    int jj = s_j;
    float im = s_invm;
    const float* Am = g_Am + (size_t)b * CH * NMASK;
    const float* Bn = g_Bn + (size_t)b * CH * NCTX;
    size_t o = ((size_t)b * NMASK + i) * CH;
#pragma unroll
    for (int c = t; c < CH; c += 256) {
        g_best[o + c] = Bn[(size_t)c * NCTX + jj];
        g_mskn[o + c] = Am[(size_t)c * NMASK + i] * im;
    }
}

// ---------------- K6: sequential scan v3 -------------------------------------
__device__ __forceinline__ float frcp(float x) {
    float r;
    asm("rcp.approx.f32 %0, %1;" : "=f"(r) : "f"(x));
    return r;
}
__device__ __forceinline__ float frsq(float x) {
    float r;
    asm("rsqrt.approx.f32 %0, %1;" : "=f"(r) : "f"(x));
    return r;
}

__device__ __forceinline__ void scan_load(const float* MN, const float* BS,
                                          size_t off, float* mn, float* bs) {
#pragma unroll
    for (int u = 0; u < 4; u++) {
        float4 a = *(const float4*)(MN + off + u * 4);
        mn[u * 4 + 0] = a.x; mn[u * 4 + 1] = a.y; mn[u * 4 + 2] = a.z; mn[u * 4 + 3] = a.w;
        float4 c = *(const float4*)(BS + off + u * 4);
        bs[u * 4 + 0] = c.x; bs[u * 4 + 1] = c.y; bs[u * 4 + 2] = c.z; bs[u * 4 + 3] = c.w;
    }
}

// cur = (s2+ * prev + mx*(nrm+eps) * best) / (s2+ + mx*(nrm+eps) + eps*nrm)
__device__ __forceinline__ void scan_step(float* q, const float* mn, const float* bs,
                                          float mx, float* GE, size_t off) {
    // balanced-tree partials for short dependency depth
    float p1[8], p2[8];
#pragma unroll
    for (int e = 0; e < 8; e++) {
        p1[e] = __fmaf_rn(q[e], q[e], q[e + 8] * q[e + 8]);
        p2[e] = __fmaf_rn(mn[e], q[e], mn[e + 8] * q[e + 8]);
    }
#pragma unroll
    for (int w = 4; w; w >>= 1)
#pragma unroll
        for (int e = 0; e < w; e++) { p1[e] += p1[e + w]; p2[e] += p2[e + w]; }
    float s1 = p1[0], s2 = p2[0];
#pragma unroll
    for (int o = 16; o; o >>= 1) {
        s1 += __shfl_xor_sync(0xffffffffu, s1, o);
        s2 += __shfl_xor_sync(0xffffffffu, s2, o);
    }
    float r   = (s1 > 0.f) ? frsq(s1) : 0.f;
    float nrm = s1 * r;                          // = sqrt(s1), 0 if s1==0
    float u   = __fmaf_rn(mx, nrm, mx * EPSF);   // mx*(nrm+eps)
    float s2p = fmaxf(s2, 0.f);
    float T   = __fmaf_rn(EPSF, nrm, s2p + u);
    float rT  = frcp(T);
    float w1 = s2p * rT, w2 = u * rT;
#pragma unroll
    for (int e = 0; e < 16; e++) q[e] = __fmaf_rn(w1, q[e], w2 * bs[e]);
#pragma unroll
    for (int uu = 0; uu < 4; uu++) {
        float4 w;
        w.x = q[uu * 4 + 0]; w.y = q[uu * 4 + 1]; w.z = q[uu * 4 + 2]; w.w = q[uu * 4 + 3];
        *(float4*)(GE + off + uu * 4) = w;
    }
}

__global__ void k_scan() {
    int b = blockIdx.x;
    int lane = threadIdx.x;
    float q[16];
#pragma unroll
    for (int e = 0; e < 16; e++) q[e] = 0.f;

    const float* MN = g_mskn + (size_t)b * NMASK * CH;
    const float* BS = g_best + (size_t)b * NMASK * CH;
    float*       GE = g_gen  + (size_t)b * NMASK * CH;
    const float* MX = g_maxc + b * NMASK;
    size_t lo = (size_t)lane * 16;

    float mnA[16], bsA[16], mnB[16], bsB[16];
    scan_load(MN, BS, lo, mnA, bsA);
    scan_load(MN, BS, (size_t)CH + lo, mnB, bsB);
    float mxA = MX[0], mxB = MX[1];

#pragma unroll 1
    for (int i = 0; i < NMASK; i += 2) {
        float mxA2 = (i + 2 < NMASK) ? MX[i + 2] : 0.f;
        float mxB2 = (i + 3 < NMASK) ? MX[i + 3] : 0.f;
        scan_step(q, mnA, bsA, mxA, GE, (size_t)i * CH + lo);
        if (i + 2 < NMASK) scan_load(MN, BS, (size_t)(i + 2) * CH + lo, mnA, bsA);
        scan_step(q, mnB, bsB, mxB, GE, (size_t)(i + 1) * CH + lo);
        if (i + 3 < NMASK) scan_load(MN, BS, (size_t)(i + 3) * CH + lo, mnB, bsB);
        mxA = mxA2; mxB = mxB2;
    }
}

// ---------------- K7: assemble output ---------------------------------------
__global__ void k_out(const float* __restrict__ x, float* __restrict__ out) {
    int idx = blockIdx.x * 256 + threadIdx.x;
    int p = idx & (HW - 1);
    int c = (idx >> 12) & (CH - 1);
    int b = idx >> 21;
    int mi = g_imask[p];
    float v = (mi >= 0) ? g_gen[(((size_t)b * NMASK) + mi) * CH + c] : x[idx];
    out[idx] = v;
}

// ---------------- launch -----------------------------------------------------
extern "C" void kernel_launch(void* const* d_in, const int* in_sizes, int n_in,
                              void* d_out, int out_size) {
    const float* x  = (const float*)d_in[0];
    const int*   np = (const int*)d_in[2];
    const int*   mp = (const int*)d_in[3];
    float*       out = (float*)d_out;

    k_part    <<<dim3(HW / 256, BATCH, NSPLIT), 256>>>(x);
    k_invall  <<<BATCH * HW / 256, 256>>>();
    k_setup   <<<1, 1024>>>(np, mp);
    k_gather  <<<dim3(CH, BATCH), 1024>>>(x, np, mp);
    k_gemm    <<<dim3(NCTX / BN, NMASK / BM, BATCH), 256>>>();
    k_finalize<<<dim3(NMASK, BATCH), 256>>>();
    k_scan    <<<BATCH, 32>>>();
    k_out     <<<(BATCH * CH * HW) / 256, 256>>>(x, out);
}

// round 4
// speedup vs baseline: 2.0326x; 1.1904x over previous
#include <cuda_runtime.h>

#define BATCH 8
#define CH    512
#define HW    4096
#define NMASK 1024
#define NCTX  3072
#define EPSF  1e-8f
#define NSPLIT 4

// ---------------- scratch (static __device__ globals; no allocation) ----------
__device__ float g_Am[BATCH * CH * NMASK];            // A gathered [b][k][i]
__device__ float g_Bn[BATCH * CH * NCTX];             // B gathered [b][k][j]
__device__ float g_best[BATCH * NMASK * CH];
__device__ float g_mskn[BATCH * NMASK * CH];
__device__ float g_gen[BATCH * NMASK * CH];
__device__ float g_part[NSPLIT][BATCH * HW];
__device__ float g_invall[BATCH * HW];
__device__ float g_invc[BATCH * NCTX];
__device__ float g_invm[BATCH * NMASK];
__device__ float g_maxc[BATCH * NMASK];
__device__ unsigned long long g_packed[BATCH * NMASK];
__device__ int   g_imask[HW];

// ---------------- K1a: partial column norms (c-split for occupancy) ---------
__global__ void k_part(const float* __restrict__ x) {
    int p = blockIdx.x * 256 + threadIdx.x;
    int b = blockIdx.y;
    int z = blockIdx.z;
    const float* base = x + ((size_t)b * CH + (size_t)z * (CH / NSPLIT)) * HW + p;
    float s = 0.f;
#pragma unroll 8
    for (int c = 0; c < CH / NSPLIT; c++) {
        float v = base[(size_t)c * HW];
        s += v * v;
    }
    g_part[z][b * HW + p] = s;
}

// ---------------- K1b: combine partials -> invall ---------------------------
__global__ void k_invall() {
    int i = blockIdx.x * 256 + threadIdx.x;
    float s = g_part[0][i] + g_part[1][i] + g_part[2][i] + g_part[3][i];
    g_invall[i] = 1.f / (sqrtf(s) + EPSF);
}

// ---------------- K2: setup --------------------------------------------------
__global__ void k_setup(const int* __restrict__ np, const int* __restrict__ mp) {
    int t = threadIdx.x;  // 1024 threads, 1 block
    for (int p = t; p < HW; p += 1024) g_imask[p] = -1;
    __syncthreads();
    g_imask[mp[t]] = t;
    for (int i = t; i < BATCH * NMASK; i += 1024) g_packed[i] = 0ull;
    for (int i = t; i < BATCH * NMASK; i += 1024) {
        int b = i / NMASK;
        g_invm[i] = g_invall[b * HW + mp[i % NMASK]];
    }
    for (int j = t; j < BATCH * NCTX; j += 1024) {
        int b = j / NCTX;
        g_invc[j] = g_invall[b * HW + np[j % NCTX]];
    }
}

// ---------------- K3: gather A (mask cols) and B (ctx cols), K-major --------
__global__ void k_gather(const float* __restrict__ x,
                         const int* __restrict__ np, const int* __restrict__ mp) {
    int k = blockIdx.x;
    int b = blockIdx.y;
    int t = threadIdx.x;        // 1024
    const float* row = x + ((size_t)b * CH + k) * HW;
    g_Am[((size_t)b * CH + k) * NMASK + t] = row[mp[t]];
#pragma unroll
    for (int j = t; j < NCTX; j += 1024)
        g_Bn[((size_t)b * CH + k) * NCTX + j] = row[np[j]];
}

// ---------------- K4: fp32 GEMM (cp.async pipeline, f32x2 FFMA) -------------
#define BM 128
#define BN 128
#define BK 16
#define NT (CH / BK)

__device__ __forceinline__ unsigned ford(float f) {
    unsigned u = __float_as_uint(f);
    return (u & 0x80000000u) ? ~u : (u | 0x80000000u);
}

__device__ __forceinline__ void cp16(void* sdst, const void* gsrc) {
    unsigned saddr = (unsigned)__cvta_generic_to_shared(sdst);
    asm volatile("cp.async.ca.shared.global [%0], [%1], 16;\n" :: "r"(saddr), "l"(gsrc));
}

__global__ void __launch_bounds__(256, 2) k_gemm() {
    __shared__ __align__(16) float As[2][BK][BM];
    __shared__ __align__(16) float Bs[2][BK][BN];

    int b  = blockIdx.z;
    int i0 = blockIdx.y * BM;
    int j0 = blockIdx.x * BN;
    int tid = threadIdx.x;
    int tx = tid & 15, ty = tid >> 4;
    int cA = tx * 4;

    const float* A  = g_Am + (size_t)b * CH * NMASK + i0;
    const float* Bp = g_Bn + (size_t)b * CH * NCTX  + j0;

    unsigned long long acc[8][4];
#pragma unroll
    for (int r = 0; r < 8; r++)
#pragma unroll
        for (int q = 0; q < 4; q++) acc[r][q] = 0ull;

#define COPY_TILE(t)                                                          \
    do {                                                                      \
        int s_ = (t) & 1;                                                     \
        const float* ga = A  + (size_t)((t) * BK + ty) * NMASK + cA;          \
        const float* gb = Bp + (size_t)((t) * BK + ty) * NCTX  + cA;          \
        cp16(&As[s_][ty][cA],      ga);                                       \
        cp16(&As[s_][ty][64 + cA], ga + 64);                                  \
        cp16(&Bs[s_][ty][cA],      gb);                                       \
        cp16(&Bs[s_][ty][64 + cA], gb + 64);                                  \
        asm volatile("cp.async.commit_group;\n");                             \
    } while (0)

    COPY_TILE(0);
    COPY_TILE(1);

#pragma unroll 1
    for (int t = 0; t < NT; t++) {
        if (t < NT - 1) asm volatile("cp.async.wait_group 1;\n");
        else            asm volatile("cp.async.wait_group 0;\n");
        __syncthreads();
        int s = t & 1;
#pragma unroll
        for (int kk = 0; kk < BK; kk++) {
            float4 a0 = *(const float4*)&As[s][kk][ty * 4];
            float4 a1 = *(const float4*)&As[s][kk][64 + ty * 4];
            ulonglong2 bv0 = *(const ulonglong2*)&Bs[s][kk][tx * 4];
            ulonglong2 bv1 = *(const ulonglong2*)&Bs[s][kk][64 + tx * 4];
            float ar[8] = {a0.x, a0.y, a0.z, a0.w, a1.x, a1.y, a1.z, a1.w};
            unsigned long long bq[4] = {bv0.x, bv0.y, bv1.x, bv1.y};
#pragma unroll
            for (int r = 0; r < 8; r++) {
                unsigned long long a2;
                asm("mov.b64 %0, {%1, %1};" : "=l"(a2) : "r"(__float_as_uint(ar[r])));
#pragma unroll
                for (int q = 0; q < 4; q++)
                    asm("fma.rn.f32x2 %0, %1, %2, %0;"
                        : "+l"(acc[r][q]) : "l"(a2), "l"(bq[q]));
            }
        }
        __syncthreads();
        if (t + 2 < NT) COPY_TILE(t + 2);
    }

    float invc[8];
#pragma unroll
    for (int g = 0; g < 2; g++)
#pragma unroll
        for (int e = 0; e < 4; e++)
            invc[g * 4 + e] = g_invc[b * NCTX + j0 + g * 64 + tx * 4 + e];

#pragma unroll
    for (int r = 0; r < 8; r++) {
        int irow = (r < 4) ? (ty * 4 + r) : (64 + ty * 4 + (r - 4));
        unsigned long long bp = 0ull;
#pragma unroll
        for (int q = 0; q < 4; q++) {
            float lo = __uint_as_float((unsigned)acc[r][q]);
            float hi = __uint_as_float((unsigned)(acc[r][q] >> 32));
            float v0 = lo * invc[q * 2];
            float v1 = hi * invc[q * 2 + 1];
            int jg = j0 + ((q >> 1) * 64) + tx * 4 + (q & 1) * 2;
            unsigned long long p0 = ((unsigned long long)ford(v0) << 32) | (unsigned)(~(unsigned)jg);
            unsigned long long p1 = ((unsigned long long)ford(v1) << 32) | (unsigned)(~(unsigned)(jg + 1));
            if (p0 > bp) bp = p0;
            if (p1 > bp) bp = p1;
        }
#pragma unroll
        for (int o = 1; o < 16; o <<= 1) {
            unsigned long long other = __shfl_xor_sync(0xffffffffu, bp, o);
            if (other > bp) bp = other;
        }
        if (tx == 0) atomicMax(&g_packed[b * NMASK + i0 + irow], bp);
    }
}

// ---------------- K5: finalize pick + gather from L2-hot scratch ------------
__global__ void k_finalize() {
    int i = blockIdx.x;
    int b = blockIdx.y;
    int t = threadIdx.x;  // 256
    __shared__ int s_j;
    __shared__ float s_invm;
    if (t == 0) {
        unsigned long long pk = g_packed[b * NMASK + i];
        unsigned j  = ~(unsigned)pk;
        unsigned ov = (unsigned)(pk >> 32);
        unsigned fb = (ov & 0x80000000u) ? (ov & 0x7fffffffu) : ~ov;
        float val = __uint_as_float(fb);
        float im  = g_invm[b * NMASK + i];
        g_maxc[b * NMASK + i] = val * im;
        s_j = (int)j;
        s_invm = im;
    }
    __syncthreads();
    int jj = s_j;
    float im = s_invm;
    const float* Am = g_Am + (size_t)b * CH * NMASK;
    const float* Bn = g_Bn + (size_t)b * CH * NCTX;
    size_t o = ((size_t)b * NMASK + i) * CH;
#pragma unroll
    for (int c = t; c < CH; c += 256) {
        g_best[o + c] = Bn[(size_t)c * NCTX + jj];
        g_mskn[o + c] = Am[(size_t)c * NMASK + i] * im;
    }
}

// ---------------- K6: sequential scan v4 (cp.async smem ring, 8 stages) -----
#define NSTAGE 8

__device__ __forceinline__ float frcp(float x) {
    float r;
    asm("rcp.approx.f32 %0, %1;" : "=f"(r) : "f"(x));
    return r;
}
__device__ __forceinline__ float frsq(float x) {
    float r;
    asm("rsqrt.approx.f32 %0, %1;" : "=f"(r) : "f"(x));
    return r;
}

__global__ void __launch_bounds__(32, 1) k_scan() {
    // ring: [stage][{mn,bs}][512 floats] = 8 * 4KB = 32KB
    __shared__ __align__(16) float ring[NSTAGE][2][CH];

    int b = blockIdx.x;
    int lane = threadIdx.x;
    float q[16];
#pragma unroll
    for (int e = 0; e < 16; e++) q[e] = 0.f;

    const float* MN = g_mskn + (size_t)b * NMASK * CH;
    const float* BS = g_best + (size_t)b * NMASK * CH;
    float*       GE = g_gen  + (size_t)b * NMASK * CH;
    const float* MX = g_maxc + b * NMASK;
    size_t lo = (size_t)lane * 16;   // this lane's 16-float slice

    // prefetch one stage: lane copies its own 64B from each array
#define SCAN_PREFETCH(i, s)                                                   \
    do {                                                                      \
        const float* pm = MN + (size_t)(i) * CH + lo;                         \
        const float* pb = BS + (size_t)(i) * CH + lo;                         \
        cp16(&ring[s][0][lo],      pm);                                       \
        cp16(&ring[s][0][lo + 4],  pm + 4);                                   \
        cp16(&ring[s][0][lo + 8],  pm + 8);                                   \
        cp16(&ring[s][0][lo + 12], pm + 12);                                  \
        cp16(&ring[s][1][lo],      pb);                                       \
        cp16(&ring[s][1][lo + 4],  pb + 4);                                   \
        cp16(&ring[s][1][lo + 8],  pb + 8);                                   \
        cp16(&ring[s][1][lo + 12], pb + 12);                                  \
        asm volatile("cp.async.commit_group;\n");                             \
    } while (0)

#pragma unroll
    for (int s = 0; s < NSTAGE; s++) SCAN_PREFETCH(s, s);

    float mx0 = MX[0];

#pragma unroll 4
    for (int i = 0; i < NMASK; i++) {
        int s = i & (NSTAGE - 1);
        float mx = mx0;
        mx0 = (i + 1 < NMASK) ? MX[i + 1] : 0.f;

        // stage i is complete once <= NSTAGE-1 groups remain in flight
        asm volatile("cp.async.wait_group %0;\n" :: "n"(NSTAGE - 1));

        float mn[16], bs[16];
#pragma unroll
        for (int u = 0; u < 4; u++) {
            float4 a = *(const float4*)&ring[s][0][lo + u * 4];
            mn[u * 4 + 0] = a.x; mn[u * 4 + 1] = a.y; mn[u * 4 + 2] = a.z; mn[u * 4 + 3] = a.w;
            float4 c = *(const float4*)&ring[s][1][lo + u * 4];
            bs[u * 4 + 0] = c.x; bs[u * 4 + 1] = c.y; bs[u * 4 + 2] = c.z; bs[u * 4 + 3] = c.w;
        }

        // recycle this stage for step i+NSTAGE (its old LDS retired ~8 steps ago)
        if (i + NSTAGE < NMASK) SCAN_PREFETCH(i + NSTAGE, s);
        else asm volatile("cp.async.commit_group;\n");  // keep group count in sync

        // balanced-tree partials
        float p1[8], p2[8];
#pragma unroll
        for (int e = 0; e < 8; e++) {
            p1[e] = __fmaf_rn(q[e], q[e], q[e + 8] * q[e + 8]);
            p2[e] = __fmaf_rn(mn[e], q[e], mn[e + 8] * q[e + 8]);
        }
#pragma unroll
        for (int w = 4; w; w >>= 1)
#pragma unroll
            for (int e = 0; e < w; e++) { p1[e] += p1[e + w]; p2[e] += p2[e + w]; }
        float s1 = p1[0], s2 = p2[0];
#pragma unroll
        for (int o = 16; o; o >>= 1) {
            s1 += __shfl_xor_sync(0xffffffffu, s1, o);
            s2 += __shfl_xor_sync(0xffffffffu, s2, o);
        }
        float r   = (s1 > 0.f) ? frsq(s1) : 0.f;
        float nrm = s1 * r;                          // sqrt(s1), 0 if s1==0
        float u   = __fmaf_rn(mx, nrm, mx * EPSF);   // mx*(nrm+eps)
        float s2p = fmaxf(s2, 0.f);
        float T   = __fmaf_rn(EPSF, nrm, s2p + u);
        float rT  = frcp(T);
        float w1 = s2p * rT, w2 = u * rT;
#pragma unroll
        for (int e = 0; e < 16; e++) q[e] = __fmaf_rn(w1, q[e], w2 * bs[e]);

        float* ge = GE + (size_t)i * CH + lo;
#pragma unroll
        for (int uu = 0; uu < 4; uu++) {
            float4 w;
            w.x = q[uu * 4 + 0]; w.y = q[uu * 4 + 1]; w.z = q[uu * 4 + 2]; w.w = q[uu * 4 + 3];
            *(float4*)(ge + uu * 4) = w;
        }
    }
}

// ---------------- K7: assemble output ---------------------------------------
__global__ void k_out(const float* __restrict__ x, float* __restrict__ out) {
    int idx = blockIdx.x * 256 + threadIdx.x;
    int p = idx & (HW - 1);
    int c = (idx >> 12) & (CH - 1);
    int b = idx >> 21;
    int mi = g_imask[p];
    float v = (mi >= 0) ? g_gen[(((size_t)b * NMASK) + mi) * CH + c] : x[idx];
    out[idx] = v;
}

// ---------------- launch -----------------------------------------------------
extern "C" void kernel_launch(void* const* d_in, const int* in_sizes, int n_in,
                              void* d_out, int out_size) {
    const float* x  = (const float*)d_in[0];
    const int*   np = (const int*)d_in[2];
    const int*   mp = (const int*)d_in[3];
    float*       out = (float*)d_out;

    k_part    <<<dim3(HW / 256, BATCH, NSPLIT), 256>>>(x);
    k_invall  <<<BATCH * HW / 256, 256>>>();
    k_setup   <<<1, 1024>>>(np, mp);
    k_gather  <<<dim3(CH, BATCH), 1024>>>(x, np, mp);
    k_gemm    <<<dim3(NCTX / BN, NMASK / BM, BATCH), 256>>>();
    k_finalize<<<dim3(NMASK, BATCH), 256>>>();
    k_scan    <<<BATCH, 32>>>();
    k_out     <<<(BATCH * CH * HW) / 256, 256>>>(x, out);
}